// round 4
// baseline (speedup 1.0000x reference)
#include <cuda_runtime.h>
#include <cuda_fp16.h>
#include <cstdint>

#define T_DIM 4096
#define H_DIM 2048
#define I_DIM 8192
#define GU_DIM (2 * I_DIM)   // 16384

// ---------------- device scratch (allocation-free rule: __device__ globals) ----
__device__ __half g_xh[(size_t)T_DIM * H_DIM];            // 16 MB
__device__ __half g_guwh[(size_t)GU_DIM * H_DIM];         // 64 MB
__device__ __half g_dwh[(size_t)H_DIM * I_DIM];           // 32 MB
__device__ __half g_interh[(size_t)T_DIM * I_DIM];        // 64 MB

// ---------------- helpers ----------------
__device__ __forceinline__ uint32_t smem_to_u32(const void* smem_ptr) {
    uint32_t addr;
    asm("{ .reg .u64 tmp; cvta.to.shared.u64 tmp, %1; cvt.u32.u64 %0, tmp; }"
        : "=r"(addr) : "l"(smem_ptr));
    return addr;
}

#define CP_ASYNC16(dst_u32, src_ptr) \
    asm volatile("cp.async.cg.shared.global [%0], [%1], 16;" \
        :: "r"(dst_u32), "l"(src_ptr) : "memory")
#define CP_ASYNC_COMMIT() asm volatile("cp.async.commit_group;" ::: "memory")
#define CP_ASYNC_WAIT_4() asm volatile("cp.async.wait_group 4;" ::: "memory")

__device__ __forceinline__ void ldmatrix_x4(uint32_t& r0, uint32_t& r1,
                                            uint32_t& r2, uint32_t& r3,
                                            uint32_t addr) {
    asm volatile("ldmatrix.sync.aligned.m8n8.x4.shared.b16 {%0,%1,%2,%3}, [%4];"
                 : "=r"(r0), "=r"(r1), "=r"(r2), "=r"(r3) : "r"(addr));
}

__device__ __forceinline__ void mma_16816(float* d, const uint32_t* a,
                                          const uint32_t* b) {
    asm volatile(
        "mma.sync.aligned.m16n8k16.row.col.f32.f16.f16.f32 "
        "{%0,%1,%2,%3}, {%4,%5,%6,%7}, {%8,%9}, {%0,%1,%2,%3};"
        : "+f"(d[0]), "+f"(d[1]), "+f"(d[2]), "+f"(d[3])
        : "r"(a[0]), "r"(a[1]), "r"(a[2]), "r"(a[3]), "r"(b[0]), "r"(b[1]));
}

// ---------------- LUT-SiLU (faithful to the 2049-entry linear interp LUT) ----
__device__ __forceinline__ float lut_silu_f(float g) {
    float t = (g + 8.0f) * 128.0f;
    t = fminf(fmaxf(t, 0.0f), 2048.0f);
    float i0 = floorf(t);
    float frac = t - i0;
    float x0 = -8.0f + i0 * 0.0078125f;
    float x1 = (i0 >= 2048.0f) ? 8.0f : (x0 + 0.0078125f);
    float l0 = x0 / (1.0f + __expf(-x0));
    float l1 = x1 / (1.0f + __expf(-x1));
    return l0 + (l1 - l0) * frac;
}

// ---------------- fp32 -> fp16 conversion ----------------
__global__ void cvt_f32_f16_kernel(const float* __restrict__ src,
                                   __half* __restrict__ dst, int n4) {
    int i = blockIdx.x * blockDim.x + threadIdx.x;
    if (i < n4) {
        float4 v = reinterpret_cast<const float4*>(src)[i];
        __half2* d2 = reinterpret_cast<__half2*>(dst) + 2 * (size_t)i;
        d2[0] = __floats2half2_rn(v.x, v.y);
        d2[1] = __floats2half2_rn(v.z, v.w);
    }
}

// ---------------- 128x{64|128}x32 HMMA GEMM, 6-stage cp.async pipeline -------
// MODE 0 (fused gate/up): CTA -> 128 rows x 64 inter cols.
//   B smem rows 0-63 = gate rows, 64-127 = up rows (same cols of inter).
//   Epilogue: inter = lut_silu(gate*sg) * (up*su), written as half.
// MODE 1 (down): CTA -> 128x128 fp32 out tile, scaled by down_scale.
// 256 threads = 8 warps in 4(M) x 2(N).
// SMEM: 64B rows, 16B chunk idx ^= (row>>1)&3 -> conflict-free ldmatrix/stores.
template <int MODE, int KT, int LDC>
__global__ void __launch_bounds__(256, 2)
gemm_hmma_kernel(const __half* __restrict__ A,
                 const __half* __restrict__ B,
                 const float* __restrict__ scales,
                 void* __restrict__ outp) {
    extern __shared__ char smem[];
    const uint32_t smem_base = smem_to_u32(smem);
    constexpr uint32_t STAGE = 16384;   // A 8KB + B 8KB
    constexpr int NC = KT / 32;         // K chunks of 32 halves
    constexpr int NSTAGE = 6;

    const int tid = threadIdx.x;
    const int wid = tid >> 5;
    const int lane = tid & 31;
    const int warp_m = wid & 3;         // m offset *32
    const int warp_n = wid >> 2;        // n offset: *32 (MODE0) / *64 (MODE1)
    const int m0 = blockIdx.y * 128;

    const __half* Ag = A + (size_t)m0 * KT;
    const __half *B0g, *B1g;            // B smem rows 0-63 / 64-127 sources
    if (MODE == 0) {
        const int j0 = blockIdx.x * 64;            // inter col base
        B0g = B + (size_t)j0 * KT;                 // gate rows
        B1g = B + (size_t)(I_DIM + j0) * KT;       // up rows
    } else {
        const int n0 = blockIdx.x * 128;
        B0g = B + (size_t)n0 * KT;
        B1g = B + (size_t)(n0 + 64) * KT;
    }

    // ---- cp.async store addressing ----
    const int st_row = tid >> 2;        // 0..63
    const int st_chunk = tid & 3;
    const uint32_t st_off =
        (uint32_t)st_row * 64u +
        (uint32_t)((st_chunk ^ ((st_row >> 1) & 3)) * 16);
    const size_t g_row_off = (size_t)st_row * KT + st_chunk * 8;

    auto load_stage = [&](int chunk) {
        const uint32_t sb = smem_base + (uint32_t)(chunk % NSTAGE) * STAGE;
        const int k0 = chunk * 32;
        CP_ASYNC16(sb + st_off,           Ag + g_row_off + k0);                    // A rows 0-63
        CP_ASYNC16(sb + st_off + 4096u,   Ag + (size_t)64 * KT + g_row_off + k0);  // A rows 64-127
        CP_ASYNC16(sb + 8192u + st_off,         B0g + g_row_off + k0);             // B rows 0-63
        CP_ASYNC16(sb + 8192u + st_off + 4096u, B1g + g_row_off + k0);             // B rows 64-127
        CP_ASYNC_COMMIT();
    };

    // ---- ldmatrix lane address components ----
    const int a_rowb = warp_m * 32 + ((lane >> 3) & 1) * 8 + (lane & 7);
    const int a_koff = (lane >> 4) & 1;
    const int a_xor = (((((lane >> 3) & 1) * 8) + (lane & 7)) >> 1) & 3;
    const int b_row_l = ((lane >> 4) & 1) * 8 + (lane & 7);  // within 16-row group
    const int b_koff = (lane >> 3) & 1;
    const int b_xor = ((b_row_l >> 1) & 3);

    float acc[2][8][4];
#pragma unroll
    for (int mi = 0; mi < 2; mi++)
#pragma unroll
        for (int ni = 0; ni < 8; ni++)
#pragma unroll
            for (int e = 0; e < 4; e++) acc[mi][ni][e] = 0.0f;

    // prologue: fill 5 of 6 stages
    load_stage(0); load_stage(1); load_stage(2); load_stage(3); load_stage(4);

#pragma unroll 1
    for (int k = 0; k < NC; ++k) {
        CP_ASYNC_WAIT_4();
        __syncthreads();
        if (k + 5 < NC) load_stage(k + 5);
        else CP_ASYNC_COMMIT();     // keep group accounting aligned

        const uint32_t sb = smem_base + (uint32_t)(k % NSTAGE) * STAGE;

#pragma unroll
        for (int ks = 0; ks < 2; ks++) {
            uint32_t a[2][4];
#pragma unroll
            for (int mi = 0; mi < 2; mi++) {
                uint32_t addr = sb + (uint32_t)((a_rowb + mi * 16) * 64) +
                                (uint32_t)(((ks * 2 + a_koff) ^ a_xor) * 16);
                ldmatrix_x4(a[mi][0], a[mi][1], a[mi][2], a[mi][3], addr);
            }
            uint32_t b[8][2];
            if (MODE == 0) {
                // gate: smem rows warp_n*32 + p*16 ; up: +64
#pragma unroll
                for (int half_sel = 0; half_sel < 2; half_sel++) {
#pragma unroll
                    for (int p = 0; p < 2; p++) {
                        int brow = half_sel * 64 + warp_n * 32 + p * 16 + b_row_l;
                        uint32_t addr = sb + 8192u + (uint32_t)(brow * 64) +
                                        (uint32_t)(((ks * 2 + b_koff) ^ b_xor) * 16);
                        uint32_t r0, r1, r2, r3;
                        ldmatrix_x4(r0, r1, r2, r3, addr);
                        int nb = half_sel * 4 + 2 * p;
                        b[nb][0] = r0; b[nb][1] = r1;
                        b[nb + 1][0] = r2; b[nb + 1][1] = r3;
                    }
                }
            } else {
#pragma unroll
                for (int p = 0; p < 4; p++) {
                    int brow = warp_n * 64 + p * 16 + b_row_l;
                    uint32_t addr = sb + 8192u + (uint32_t)(brow * 64) +
                                    (uint32_t)(((ks * 2 + b_koff) ^ b_xor) * 16);
                    uint32_t r0, r1, r2, r3;
                    ldmatrix_x4(r0, r1, r2, r3, addr);
                    b[2 * p][0] = r0; b[2 * p][1] = r1;
                    b[2 * p + 1][0] = r2; b[2 * p + 1][1] = r3;
                }
            }
#pragma unroll
            for (int mi = 0; mi < 2; mi++)
#pragma unroll
                for (int ni = 0; ni < 8; ni++)
                    mma_16816(acc[mi][ni], a[mi], b[ni]);
        }
    }

    // ---- epilogue ----
    const int gr = lane >> 2;
    const int gc = (lane & 3) * 2;
    if (MODE == 0) {
        __half* out = reinterpret_cast<__half*>(outp);
        const int j0 = blockIdx.x * 64;
#pragma unroll
        for (int mi = 0; mi < 2; mi++) {
#pragma unroll
            for (int nb = 0; nb < 4; nb++) {
                const int row = m0 + warp_m * 32 + mi * 16 + gr;
                const int col = j0 + warp_n * 32 + nb * 8 + gc;
                const float sg0 = __ldg(&scales[col]);
                const float sg1 = __ldg(&scales[col + 1]);
                const float su0 = __ldg(&scales[I_DIM + col]);
                const float su1 = __ldg(&scales[I_DIM + col + 1]);
                const float* g = acc[mi][nb];
                const float* u = acc[mi][nb + 4];
                float v0 = lut_silu_f(g[0] * sg0) * (u[0] * su0);
                float v1 = lut_silu_f(g[1] * sg1) * (u[1] * su1);
                float v2 = lut_silu_f(g[2] * sg0) * (u[2] * su0);
                float v3 = lut_silu_f(g[3] * sg1) * (u[3] * su1);
                *reinterpret_cast<__half2*>(&out[(size_t)row * LDC + col]) =
                    __floats2half2_rn(v0, v1);
                *reinterpret_cast<__half2*>(&out[(size_t)(row + 8) * LDC + col]) =
                    __floats2half2_rn(v2, v3);
            }
        }
    } else {
        float* out = reinterpret_cast<float*>(outp);
        const int n0 = blockIdx.x * 128;
#pragma unroll
        for (int mi = 0; mi < 2; mi++) {
#pragma unroll
            for (int ni = 0; ni < 8; ni++) {
                const int row = m0 + warp_m * 32 + mi * 16 + gr;
                const int col = n0 + warp_n * 64 + ni * 8 + gc;
                const float s0 = __ldg(&scales[col]);
                const float s1 = __ldg(&scales[col + 1]);
                *reinterpret_cast<float2*>(&out[(size_t)row * LDC + col]) =
                    make_float2(acc[mi][ni][0] * s0, acc[mi][ni][1] * s1);
                *reinterpret_cast<float2*>(&out[(size_t)(row + 8) * LDC + col]) =
                    make_float2(acc[mi][ni][2] * s0, acc[mi][ni][3] * s1);
            }
        }
    }
}

// ---------------- launch ----------------
extern "C" void kernel_launch(void* const* d_in, const int* in_sizes, int n_in,
                              void* d_out, int out_size) {
    const float* x   = (const float*)d_in[0];
    const float* guw = (const float*)d_in[1];
    const float* gus = (const float*)d_in[2];
    const float* dw  = (const float*)d_in[3];
    const float* ds  = (const float*)d_in[4];

    __half *xh, *guwh, *dwh, *interh;
    cudaGetSymbolAddress((void**)&xh, g_xh);
    cudaGetSymbolAddress((void**)&guwh, g_guwh);
    cudaGetSymbolAddress((void**)&dwh, g_dwh);
    cudaGetSymbolAddress((void**)&interh, g_interh);

    // fp32 -> fp16 prep (weights are int-valued: exact in fp16)
    {
        int n4 = T_DIM * H_DIM / 4;
        cvt_f32_f16_kernel<<<(n4 + 255) / 256, 256>>>(x, xh, n4);
    }
    {
        int n4 = GU_DIM * H_DIM / 4;
        cvt_f32_f16_kernel<<<(n4 + 255) / 256, 256>>>(guw, guwh, n4);
    }
    {
        int n4 = H_DIM * I_DIM / 4;
        cvt_f32_f16_kernel<<<(n4 + 255) / 256, 256>>>(dw, dwh, n4);
    }

    const int SMEM_BYTES = 6 * 16384;   // 96 KB
    cudaFuncSetAttribute(gemm_hmma_kernel<0, H_DIM, I_DIM>,
                         cudaFuncAttributeMaxDynamicSharedMemorySize, SMEM_BYTES);
    cudaFuncSetAttribute(gemm_hmma_kernel<1, I_DIM, H_DIM>,
                         cudaFuncAttributeMaxDynamicSharedMemorySize, SMEM_BYTES);

    // GEMM1 fused: inter = lut_silu(x@gw^T*sg) * (x@uw^T*su)  (4096x8192, K=2048)
    {
        dim3 grid(I_DIM / 64, T_DIM / 128);
        gemm_hmma_kernel<0, H_DIM, I_DIM><<<grid, 256, SMEM_BYTES>>>(
            xh, guwh, gus, interh);
    }
    // GEMM2: out = inter @ down_w^T * ds    (4096x2048, K=8192)
    {
        dim3 grid(H_DIM / 128, T_DIM / 128);
        gemm_hmma_kernel<1, I_DIM, H_DIM><<<grid, 256, SMEM_BYTES>>>(
            interh, dwh, ds, d_out);
    }
    (void)in_sizes; (void)n_in; (void)out_size;
}

// round 5
// speedup vs baseline: 1.0784x; 1.0784x over previous
#include <cuda_runtime.h>
#include <cuda_fp16.h>
#include <cstdint>

#define T_DIM 4096
#define H_DIM 2048
#define I_DIM 8192
#define GU_DIM (2 * I_DIM)   // 16384

// ---------------- device scratch (allocation-free rule: __device__ globals) ----
__device__ __half g_xh[(size_t)T_DIM * H_DIM];            // 16 MB
__device__ __half g_guwh[(size_t)GU_DIM * H_DIM];         // 64 MB
__device__ __half g_dwh[(size_t)H_DIM * I_DIM];           // 32 MB
__device__ __half g_interh[(size_t)T_DIM * I_DIM];        // 64 MB

// ---------------- helpers ----------------
__device__ __forceinline__ uint32_t smem_to_u32(const void* smem_ptr) {
    uint32_t addr;
    asm("{ .reg .u64 tmp; cvta.to.shared.u64 tmp, %1; cvt.u32.u64 %0, tmp; }"
        : "=r"(addr) : "l"(smem_ptr));
    return addr;
}

#define CP_ASYNC16(dst_u32, src_ptr) \
    asm volatile("cp.async.cg.shared.global [%0], [%1], 16;" \
        :: "r"(dst_u32), "l"(src_ptr) : "memory")
#define CP_ASYNC_COMMIT() asm volatile("cp.async.commit_group;" ::: "memory")
#define CP_ASYNC_WAIT_2() asm volatile("cp.async.wait_group 2;" ::: "memory")

__device__ __forceinline__ void ldmatrix_x4(uint32_t& r0, uint32_t& r1,
                                            uint32_t& r2, uint32_t& r3,
                                            uint32_t addr) {
    asm volatile("ldmatrix.sync.aligned.m8n8.x4.shared.b16 {%0,%1,%2,%3}, [%4];"
                 : "=r"(r0), "=r"(r1), "=r"(r2), "=r"(r3) : "r"(addr));
}

__device__ __forceinline__ void mma_16816(float* d, const uint32_t* a,
                                          const uint32_t* b) {
    asm volatile(
        "mma.sync.aligned.m16n8k16.row.col.f32.f16.f16.f32 "
        "{%0,%1,%2,%3}, {%4,%5,%6,%7}, {%8,%9}, {%0,%1,%2,%3};"
        : "+f"(d[0]), "+f"(d[1]), "+f"(d[2]), "+f"(d[3])
        : "r"(a[0]), "r"(a[1]), "r"(a[2]), "r"(a[3]), "r"(b[0]), "r"(b[1]));
}

// ---------------- LUT-SiLU (faithful to the 2049-entry linear interp LUT) ----
__device__ __forceinline__ float lut_silu_f(float g) {
    float t = (g + 8.0f) * 128.0f;
    t = fminf(fmaxf(t, 0.0f), 2048.0f);
    float i0 = floorf(t);
    float frac = t - i0;
    float x0 = -8.0f + i0 * 0.0078125f;
    float x1 = (i0 >= 2048.0f) ? 8.0f : (x0 + 0.0078125f);
    float l0 = x0 / (1.0f + __expf(-x0));
    float l1 = x1 / (1.0f + __expf(-x1));
    return l0 + (l1 - l0) * frac;
}

// ---------------- fp32 -> fp16 conversion ----------------
__global__ void cvt_f32_f16_kernel(const float* __restrict__ src,
                                   __half* __restrict__ dst, int n4) {
    int i = blockIdx.x * blockDim.x + threadIdx.x;
    if (i < n4) {
        float4 v = reinterpret_cast<const float4*>(src)[i];
        __half2* d2 = reinterpret_cast<__half2*>(dst) + 2 * (size_t)i;
        d2[0] = __floats2half2_rn(v.x, v.y);
        d2[1] = __floats2half2_rn(v.z, v.w);
    }
}

// ---------------- 128x{64|128}x32 HMMA GEMM, 4-stage cp.async pipeline -------
// R3-proven mainloop (4 stages, &3, wait_group 2, prefetch after MMA) +
// R4's fused gate/up epilogue.
// MODE 0 (fused gate/up): CTA -> 128 rows x 64 inter cols.
//   B smem rows 0-63 = gate rows, 64-127 = up rows (same inter cols).
//   Epilogue: inter = lut_silu(gate*sg) * (up*su), written as half.
// MODE 1 (down): CTA -> 128x128 fp32 out tile, scaled by down_scale.
// 256 threads = 8 warps in 4(M) x 2(N).
// SMEM: 64B rows, 16B chunk idx ^= (row>>1)&3 -> conflict-free ldmatrix/stores.
template <int MODE, int KT, int LDC>
__global__ void __launch_bounds__(256, 2)
gemm_hmma_kernel(const __half* __restrict__ A,
                 const __half* __restrict__ B,
                 const float* __restrict__ scales,
                 void* __restrict__ outp) {
    extern __shared__ char smem[];
    const uint32_t smem_base = smem_to_u32(smem);
    constexpr uint32_t STAGE = 16384;   // A 8KB + B 8KB
    constexpr int NC = KT / 32;         // K chunks of 32 halves

    const int tid = threadIdx.x;
    const int wid = tid >> 5;
    const int lane = tid & 31;
    const int warp_m = wid & 3;         // m offset *32
    const int warp_n = wid >> 2;        // n offset: *32 (MODE0) / *64 (MODE1)
    const int m0 = blockIdx.y * 128;

    const __half* Ag = A + (size_t)m0 * KT;
    const __half *B0g, *B1g;            // B smem rows 0-63 / 64-127 sources
    if (MODE == 0) {
        const int j0 = blockIdx.x * 64;            // inter col base
        B0g = B + (size_t)j0 * KT;                 // gate rows
        B1g = B + (size_t)(I_DIM + j0) * KT;       // up rows
    } else {
        const int n0 = blockIdx.x * 128;
        B0g = B + (size_t)n0 * KT;
        B1g = B + (size_t)(n0 + 64) * KT;
    }

    // ---- cp.async store addressing ----
    const int st_row = tid >> 2;        // 0..63
    const int st_chunk = tid & 3;
    const uint32_t st_off =
        (uint32_t)st_row * 64u +
        (uint32_t)((st_chunk ^ ((st_row >> 1) & 3)) * 16);
    const size_t g_row_off = (size_t)st_row * KT + st_chunk * 8;

    auto load_stage = [&](int chunk) {
        const uint32_t sb = smem_base + (uint32_t)(chunk & 3) * STAGE;
        const int k0 = chunk * 32;
        CP_ASYNC16(sb + st_off,           Ag + g_row_off + k0);
        CP_ASYNC16(sb + st_off + 4096u,   Ag + (size_t)64 * KT + g_row_off + k0);
        CP_ASYNC16(sb + 8192u + st_off,         B0g + g_row_off + k0);
        CP_ASYNC16(sb + 8192u + st_off + 4096u, B1g + g_row_off + k0);
        CP_ASYNC_COMMIT();
    };

    // ---- ldmatrix lane address components ----
    const int a_rowb = warp_m * 32 + ((lane >> 3) & 1) * 8 + (lane & 7);
    const int a_koff = (lane >> 4) & 1;
    const int a_xor = (((((lane >> 3) & 1) * 8) + (lane & 7)) >> 1) & 3;
    const int b_row_l = ((lane >> 4) & 1) * 8 + (lane & 7);  // within 16-row group
    const int b_koff = (lane >> 3) & 1;
    const int b_xor = ((b_row_l >> 1) & 3);

    float acc[2][8][4];
#pragma unroll
    for (int mi = 0; mi < 2; mi++)
#pragma unroll
        for (int ni = 0; ni < 8; ni++)
#pragma unroll
            for (int e = 0; e < 4; e++) acc[mi][ni][e] = 0.0f;

    // prologue: fill 3 of 4 stages
    load_stage(0); load_stage(1); load_stage(2);

#pragma unroll 1
    for (int k = 0; k < NC; ++k) {
        CP_ASYNC_WAIT_2();
        __syncthreads();
        const uint32_t sb = smem_base + (uint32_t)(k & 3) * STAGE;

#pragma unroll
        for (int ks = 0; ks < 2; ks++) {
            uint32_t a[2][4];
#pragma unroll
            for (int mi = 0; mi < 2; mi++) {
                uint32_t addr = sb + (uint32_t)((a_rowb + mi * 16) * 64) +
                                (uint32_t)(((ks * 2 + a_koff) ^ a_xor) * 16);
                ldmatrix_x4(a[mi][0], a[mi][1], a[mi][2], a[mi][3], addr);
            }
            uint32_t b[8][2];
            if (MODE == 0) {
                // gate: smem rows warp_n*32 + p*16 ; up: +64
#pragma unroll
                for (int half_sel = 0; half_sel < 2; half_sel++) {
#pragma unroll
                    for (int p = 0; p < 2; p++) {
                        int brow = half_sel * 64 + warp_n * 32 + p * 16 + b_row_l;
                        uint32_t addr = sb + 8192u + (uint32_t)(brow * 64) +
                                        (uint32_t)(((ks * 2 + b_koff) ^ b_xor) * 16);
                        uint32_t r0, r1, r2, r3;
                        ldmatrix_x4(r0, r1, r2, r3, addr);
                        int nb = half_sel * 4 + 2 * p;
                        b[nb][0] = r0; b[nb][1] = r1;
                        b[nb + 1][0] = r2; b[nb + 1][1] = r3;
                    }
                }
            } else {
#pragma unroll
                for (int p = 0; p < 4; p++) {
                    int brow = warp_n * 64 + p * 16 + b_row_l;
                    uint32_t addr = sb + 8192u + (uint32_t)(brow * 64) +
                                    (uint32_t)(((ks * 2 + b_koff) ^ b_xor) * 16);
                    uint32_t r0, r1, r2, r3;
                    ldmatrix_x4(r0, r1, r2, r3, addr);
                    b[2 * p][0] = r0; b[2 * p][1] = r1;
                    b[2 * p + 1][0] = r2; b[2 * p + 1][1] = r3;
                }
            }
#pragma unroll
            for (int mi = 0; mi < 2; mi++)
#pragma unroll
                for (int ni = 0; ni < 8; ni++)
                    mma_16816(acc[mi][ni], a[mi], b[ni]);
        }

        if (k + 3 < NC) load_stage(k + 3);
        else CP_ASYNC_COMMIT();   // keep group accounting aligned
    }

    // ---- epilogue ----
    const int gr = lane >> 2;
    const int gc = (lane & 3) * 2;
    if (MODE == 0) {
        __half* out = reinterpret_cast<__half*>(outp);
        const int j0 = blockIdx.x * 64;
#pragma unroll
        for (int mi = 0; mi < 2; mi++) {
#pragma unroll
            for (int nb = 0; nb < 4; nb++) {
                const int row = m0 + warp_m * 32 + mi * 16 + gr;
                const int col = j0 + warp_n * 32 + nb * 8 + gc;
                const float sg0 = __ldg(&scales[col]);
                const float sg1 = __ldg(&scales[col + 1]);
                const float su0 = __ldg(&scales[I_DIM + col]);
                const float su1 = __ldg(&scales[I_DIM + col + 1]);
                const float* g = acc[mi][nb];
                const float* u = acc[mi][nb + 4];
                float v0 = lut_silu_f(g[0] * sg0) * (u[0] * su0);
                float v1 = lut_silu_f(g[1] * sg1) * (u[1] * su1);
                float v2 = lut_silu_f(g[2] * sg0) * (u[2] * su0);
                float v3 = lut_silu_f(g[3] * sg1) * (u[3] * su1);
                *reinterpret_cast<__half2*>(&out[(size_t)row * LDC + col]) =
                    __floats2half2_rn(v0, v1);
                *reinterpret_cast<__half2*>(&out[(size_t)(row + 8) * LDC + col]) =
                    __floats2half2_rn(v2, v3);
            }
        }
    } else {
        float* out = reinterpret_cast<float*>(outp);
        const int n0 = blockIdx.x * 128;
#pragma unroll
        for (int mi = 0; mi < 2; mi++) {
#pragma unroll
            for (int ni = 0; ni < 8; ni++) {
                const int row = m0 + warp_m * 32 + mi * 16 + gr;
                const int col = n0 + warp_n * 64 + ni * 8 + gc;
                const float s0 = __ldg(&scales[col]);
                const float s1 = __ldg(&scales[col + 1]);
                *reinterpret_cast<float2*>(&out[(size_t)row * LDC + col]) =
                    make_float2(acc[mi][ni][0] * s0, acc[mi][ni][1] * s1);
                *reinterpret_cast<float2*>(&out[(size_t)(row + 8) * LDC + col]) =
                    make_float2(acc[mi][ni][2] * s0, acc[mi][ni][3] * s1);
            }
        }
    }
}

// ---------------- launch ----------------
extern "C" void kernel_launch(void* const* d_in, const int* in_sizes, int n_in,
                              void* d_out, int out_size) {
    const float* x   = (const float*)d_in[0];
    const float* guw = (const float*)d_in[1];
    const float* gus = (const float*)d_in[2];
    const float* dw  = (const float*)d_in[3];
    const float* ds  = (const float*)d_in[4];

    __half *xh, *guwh, *dwh, *interh;
    cudaGetSymbolAddress((void**)&xh, g_xh);
    cudaGetSymbolAddress((void**)&guwh, g_guwh);
    cudaGetSymbolAddress((void**)&dwh, g_dwh);
    cudaGetSymbolAddress((void**)&interh, g_interh);

    // fp32 -> fp16 prep (weights are int-valued: exact in fp16)
    {
        int n4 = T_DIM * H_DIM / 4;
        cvt_f32_f16_kernel<<<(n4 + 255) / 256, 256>>>(x, xh, n4);
    }
    {
        int n4 = GU_DIM * H_DIM / 4;
        cvt_f32_f16_kernel<<<(n4 + 255) / 256, 256>>>(guw, guwh, n4);
    }
    {
        int n4 = H_DIM * I_DIM / 4;
        cvt_f32_f16_kernel<<<(n4 + 255) / 256, 256>>>(dw, dwh, n4);
    }

    const int SMEM_BYTES = 4 * 16384;   // 64 KB
    cudaFuncSetAttribute(gemm_hmma_kernel<0, H_DIM, I_DIM>,
                         cudaFuncAttributeMaxDynamicSharedMemorySize, SMEM_BYTES);
    cudaFuncSetAttribute(gemm_hmma_kernel<1, I_DIM, H_DIM>,
                         cudaFuncAttributeMaxDynamicSharedMemorySize, SMEM_BYTES);

    // GEMM1 fused: inter = lut_silu(x@gw^T*sg) * (x@uw^T*su)  (4096x8192, K=2048)
    {
        dim3 grid(I_DIM / 64, T_DIM / 128);
        gemm_hmma_kernel<0, H_DIM, I_DIM><<<grid, 256, SMEM_BYTES>>>(
            xh, guwh, gus, interh);
    }
    // GEMM2: out = inter @ down_w^T * ds    (4096x2048, K=8192)
    {
        dim3 grid(H_DIM / 128, T_DIM / 128);
        gemm_hmma_kernel<1, I_DIM, H_DIM><<<grid, 256, SMEM_BYTES>>>(
            interh, dwh, ds, d_out);
    }
    (void)in_sizes; (void)n_in; (void)out_size;
}

// round 7
// speedup vs baseline: 1.0952x; 1.0156x over previous
#include <cuda_runtime.h>
#include <cuda_fp16.h>
#include <cstdint>

#define T_DIM 4096
#define H_DIM 2048
#define I_DIM 8192
#define GU_DIM (2 * I_DIM)   // 16384

// ---------------- device scratch (allocation-free rule: __device__ globals) ----
__device__ __half g_xh[(size_t)T_DIM * H_DIM];            // 16 MB
__device__ __half g_guwh[(size_t)GU_DIM * H_DIM];         // 64 MB
__device__ __half g_dwh[(size_t)H_DIM * I_DIM];           // 32 MB
__device__ __half g_interh[(size_t)T_DIM * I_DIM];        // 64 MB

// ---------------- helpers ----------------
__device__ __forceinline__ uint32_t smem_to_u32(const void* smem_ptr) {
    uint32_t addr;
    asm("{ .reg .u64 tmp; cvta.to.shared.u64 tmp, %1; cvt.u32.u64 %0, tmp; }"
        : "=r"(addr) : "l"(smem_ptr));
    return addr;
}

#define CP_ASYNC16(dst_u32, src_ptr) \
    asm volatile("cp.async.cg.shared.global [%0], [%1], 16;" \
        :: "r"(dst_u32), "l"(src_ptr) : "memory")
#define CP_ASYNC_COMMIT() asm volatile("cp.async.commit_group;" ::: "memory")
#define CP_ASYNC_WAIT_2() asm volatile("cp.async.wait_group 2;" ::: "memory")

__device__ __forceinline__ void ldmatrix_x4(uint32_t& r0, uint32_t& r1,
                                            uint32_t& r2, uint32_t& r3,
                                            uint32_t addr) {
    asm volatile("ldmatrix.sync.aligned.m8n8.x4.shared.b16 {%0,%1,%2,%3}, [%4];"
                 : "=r"(r0), "=r"(r1), "=r"(r2), "=r"(r3) : "r"(addr));
}

__device__ __forceinline__ void mma_16816(float* d, const uint32_t* a,
                                          const uint32_t* b) {
    asm volatile(
        "mma.sync.aligned.m16n8k16.row.col.f32.f16.f16.f32 "
        "{%0,%1,%2,%3}, {%4,%5,%6,%7}, {%8,%9}, {%0,%1,%2,%3};"
        : "+f"(d[0]), "+f"(d[1]), "+f"(d[2]), "+f"(d[3])
        : "r"(a[0]), "r"(a[1]), "r"(a[2]), "r"(a[3]), "r"(b[0]), "r"(b[1]));
}

// ---------------- LUT-SiLU (faithful to the 2049-entry linear interp LUT) ----
__device__ __forceinline__ float lut_silu_f(float g) {
    float t = (g + 8.0f) * 128.0f;
    t = fminf(fmaxf(t, 0.0f), 2048.0f);
    float i0 = floorf(t);
    float frac = t - i0;
    float x0 = -8.0f + i0 * 0.0078125f;
    float x1 = (i0 >= 2048.0f) ? 8.0f : (x0 + 0.0078125f);
    float l0 = x0 / (1.0f + __expf(-x0));
    float l1 = x1 / (1.0f + __expf(-x1));
    return l0 + (l1 - l0) * frac;
}

// ---------------- fp32 -> fp16 conversion ----------------
__global__ void cvt_f32_f16_kernel(const float* __restrict__ src,
                                   __half* __restrict__ dst, int n4) {
    int i = blockIdx.x * blockDim.x + threadIdx.x;
    if (i < n4) {
        float4 v = reinterpret_cast<const float4*>(src)[i];
        __half2* d2 = reinterpret_cast<__half2*>(dst) + 2 * (size_t)i;
        d2[0] = __floats2half2_rn(v.x, v.y);
        d2[1] = __floats2half2_rn(v.z, v.w);
    }
}

// ---------------- 128x{64|128}x32 HMMA GEMM, 4-stage cp.async pipeline -------
// R3 schedule (4 stages, wait_group 2, prefetch after MMA) + fused gate/up
// epilogue + fully precomputed ldmatrix addresses + k-loop unrolled by 4
// (stage offsets become compile-time immediates).
template <int MODE, int KT, int LDC>
__global__ void __launch_bounds__(256, 2)
gemm_hmma_kernel(const __half* __restrict__ A,
                 const __half* __restrict__ B,
                 const float* __restrict__ scales,
                 void* __restrict__ outp) {
    extern __shared__ char smem[];
    const uint32_t smem_base = smem_to_u32(smem);
    constexpr uint32_t STAGE = 16384;   // A 8KB + B 8KB
    constexpr int NC = KT / 32;         // K chunks of 32 halves (64 or 256)

    const int tid = threadIdx.x;
    const int wid = tid >> 5;
    const int lane = tid & 31;
    const int warp_m = wid & 3;         // m offset *32
    const int warp_n = wid >> 2;        // n offset: *32 (MODE0) / *64 (MODE1)
    const int m0 = blockIdx.y * 128;

    const __half* Ag = A + (size_t)m0 * KT;
    const __half *B0g, *B1g;            // B smem rows 0-63 / 64-127 sources
    if (MODE == 0) {
        const int j0 = blockIdx.x * 64;            // inter col base
        B0g = B + (size_t)j0 * KT;                 // gate rows
        B1g = B + (size_t)(I_DIM + j0) * KT;       // up rows
    } else {
        const int n0 = blockIdx.x * 128;
        B0g = B + (size_t)n0 * KT;
        B1g = B + (size_t)(n0 + 64) * KT;
    }

    // ---- cp.async store addressing ----
    const int st_row = tid >> 2;        // 0..63
    const int st_chunk = tid & 3;
    const uint32_t st_off =
        (uint32_t)st_row * 64u +
        (uint32_t)((st_chunk ^ ((st_row >> 1) & 3)) * 16);
    const size_t g_row_off = (size_t)st_row * KT + st_chunk * 8;

    const uint32_t stA0 = smem_base + st_off;
    const uint32_t stA1 = smem_base + st_off + 4096u;
    const uint32_t stB0 = smem_base + 8192u + st_off;
    const uint32_t stB1 = smem_base + 8192u + st_off + 4096u;

    auto load_stage_at = [&](uint32_t stage_byte_off, int chunk) {
        const int k0 = chunk * 32;
        CP_ASYNC16(stA0 + stage_byte_off, Ag + g_row_off + k0);
        CP_ASYNC16(stA1 + stage_byte_off, Ag + (size_t)64 * KT + g_row_off + k0);
        CP_ASYNC16(stB0 + stage_byte_off, B0g + g_row_off + k0);
        CP_ASYNC16(stB1 + stage_byte_off, B1g + g_row_off + k0);
        CP_ASYNC_COMMIT();
    };

    // ---- precomputed ldmatrix addresses (stage-0 absolute; add kk*STAGE) ----
    const int a_rowb = warp_m * 32 + ((lane >> 3) & 1) * 8 + (lane & 7);
    const int a_koff = (lane >> 4) & 1;
    const int a_xor = (((((lane >> 3) & 1) * 8) + (lane & 7)) >> 1) & 3;
    const int b_row_l = ((lane >> 4) & 1) * 8 + (lane & 7);
    const int b_koff = (lane >> 3) & 1;
    const int b_xor = ((b_row_l >> 1) & 3);

    uint32_t a_base[2], b_base[4], ak16[2], bk16[2];
#pragma unroll
    for (int mi = 0; mi < 2; mi++)
        a_base[mi] = smem_base + (uint32_t)((a_rowb + mi * 16) * 64);
#pragma unroll
    for (int ks = 0; ks < 2; ks++) {
        ak16[ks] = (uint32_t)(((ks * 2 + a_koff) ^ a_xor) * 16);
        bk16[ks] = (uint32_t)(((ks * 2 + b_koff) ^ b_xor) * 16);
    }
    if (MODE == 0) {
        // idx = half_sel*2 + p ; rows: half_sel*64 + warp_n*32 + p*16 + b_row_l
#pragma unroll
        for (int idx = 0; idx < 4; idx++) {
            int half_sel = idx >> 1, p = idx & 1;
            int brow = half_sel * 64 + warp_n * 32 + p * 16 + b_row_l;
            b_base[idx] = smem_base + 8192u + (uint32_t)(brow * 64);
        }
    } else {
#pragma unroll
        for (int p = 0; p < 4; p++) {
            int brow = warp_n * 64 + p * 16 + b_row_l;
            b_base[p] = smem_base + 8192u + (uint32_t)(brow * 64);
        }
    }

    float acc[2][8][4];
#pragma unroll
    for (int mi = 0; mi < 2; mi++)
#pragma unroll
        for (int ni = 0; ni < 8; ni++)
#pragma unroll
            for (int e = 0; e < 4; e++) acc[mi][ni][e] = 0.0f;

    // prologue: fill 3 of 4 stages
    load_stage_at(0 * STAGE, 0);
    load_stage_at(1 * STAGE, 1);
    load_stage_at(2 * STAGE, 2);

#pragma unroll 1
    for (int kb = 0; kb < NC; kb += 4) {
#pragma unroll
        for (int kk = 0; kk < 4; kk++) {
            const int k = kb + kk;
            const uint32_t soff = (uint32_t)kk * STAGE;  // compile-time immediate

            CP_ASYNC_WAIT_2();
            __syncthreads();

#pragma unroll
            for (int ks = 0; ks < 2; ks++) {
                uint32_t a[2][4];
#pragma unroll
                for (int mi = 0; mi < 2; mi++)
                    ldmatrix_x4(a[mi][0], a[mi][1], a[mi][2], a[mi][3],
                                a_base[mi] + soff + ak16[ks]);
                uint32_t b[8][2];
                if (MODE == 0) {
#pragma unroll
                    for (int idx = 0; idx < 4; idx++) {
                        uint32_t r0, r1, r2, r3;
                        ldmatrix_x4(r0, r1, r2, r3, b_base[idx] + soff + bk16[ks]);
                        // idx = half_sel*2+p -> nb = half_sel*4 + 2*p
                        const int nb = (idx >> 1) * 4 + (idx & 1) * 2;
                        b[nb][0] = r0; b[nb][1] = r1;
                        b[nb + 1][0] = r2; b[nb + 1][1] = r3;
                    }
                } else {
#pragma unroll
                    for (int p = 0; p < 4; p++) {
                        uint32_t r0, r1, r2, r3;
                        ldmatrix_x4(r0, r1, r2, r3, b_base[p] + soff + bk16[ks]);
                        b[2 * p][0] = r0; b[2 * p][1] = r1;
                        b[2 * p + 1][0] = r2; b[2 * p + 1][1] = r3;
                    }
                }
#pragma unroll
                for (int mi = 0; mi < 2; mi++)
#pragma unroll
                    for (int ni = 0; ni < 8; ni++)
                        mma_16816(acc[mi][ni], a[mi], b[ni]);
            }

            if (k + 3 < NC)
                load_stage_at((uint32_t)((kk + 3) & 3) * STAGE, k + 3);
            else
                CP_ASYNC_COMMIT();   // keep group accounting aligned
        }
    }

    // ---- epilogue ----
    const int gr = lane >> 2;
    const int gc = (lane & 3) * 2;
    if (MODE == 0) {
        __half* out = reinterpret_cast<__half*>(outp);
        const int j0 = blockIdx.x * 64;
#pragma unroll
        for (int mi = 0; mi < 2; mi++) {
#pragma unroll
            for (int nb = 0; nb < 4; nb++) {
                const int row = m0 + warp_m * 32 + mi * 16 + gr;
                const int col = j0 + warp_n * 32 + nb * 8 + gc;
                const float sg0 = __ldg(&scales[col]);
                const float sg1 = __ldg(&scales[col + 1]);
                const float su0 = __ldg(&scales[I_DIM + col]);
                const float su1 = __ldg(&scales[I_DIM + col + 1]);
                const float* g = acc[mi][nb];
                const float* u = acc[mi][nb + 4];
                float v0 = lut_silu_f(g[0] * sg0) * (u[0] * su0);
                float v1 = lut_silu_f(g[1] * sg1) * (u[1] * su1);
                float v2 = lut_silu_f(g[2] * sg0) * (u[2] * su0);
                float v3 = lut_silu_f(g[3] * sg1) * (u[3] * su1);
                *reinterpret_cast<__half2*>(&out[(size_t)row * LDC + col]) =
                    __floats2half2_rn(v0, v1);
                *reinterpret_cast<__half2*>(&out[(size_t)(row + 8) * LDC + col]) =
                    __floats2half2_rn(v2, v3);
            }
        }
    } else {
        float* out = reinterpret_cast<float*>(outp);
        const int n0 = blockIdx.x * 128;
#pragma unroll
        for (int mi = 0; mi < 2; mi++) {
#pragma unroll
            for (int ni = 0; ni < 8; ni++) {
                const int row = m0 + warp_m * 32 + mi * 16 + gr;
                const int col = n0 + warp_n * 64 + ni * 8 + gc;
                const float s0 = __ldg(&scales[col]);
                const float s1 = __ldg(&scales[col + 1]);
                *reinterpret_cast<float2*>(&out[(size_t)row * LDC + col]) =
                    make_float2(acc[mi][ni][0] * s0, acc[mi][ni][1] * s1);
                *reinterpret_cast<float2*>(&out[(size_t)(row + 8) * LDC + col]) =
                    make_float2(acc[mi][ni][2] * s0, acc[mi][ni][3] * s1);
            }
        }
    }
}

// ---------------- launch ----------------
extern "C" void kernel_launch(void* const* d_in, const int* in_sizes, int n_in,
                              void* d_out, int out_size) {
    const float* x   = (const float*)d_in[0];
    const float* guw = (const float*)d_in[1];
    const float* gus = (const float*)d_in[2];
    const float* dw  = (const float*)d_in[3];
    const float* ds  = (const float*)d_in[4];

    __half *xh, *guwh, *dwh, *interh;
    cudaGetSymbolAddress((void**)&xh, g_xh);
    cudaGetSymbolAddress((void**)&guwh, g_guwh);
    cudaGetSymbolAddress((void**)&dwh, g_dwh);
    cudaGetSymbolAddress((void**)&interh, g_interh);

    // fp32 -> fp16 prep (weights are int-valued: exact in fp16)
    {
        int n4 = T_DIM * H_DIM / 4;
        cvt_f32_f16_kernel<<<(n4 + 255) / 256, 256>>>(x, xh, n4);
    }
    {
        int n4 = GU_DIM * H_DIM / 4;
        cvt_f32_f16_kernel<<<(n4 + 255) / 256, 256>>>(guw, guwh, n4);
    }
    {
        int n4 = H_DIM * I_DIM / 4;
        cvt_f32_f16_kernel<<<(n4 + 255) / 256, 256>>>(dw, dwh, n4);
    }

    const int SMEM_BYTES = 4 * 16384;   // 64 KB
    cudaFuncSetAttribute(gemm_hmma_kernel<0, H_DIM, I_DIM>,
                         cudaFuncAttributeMaxDynamicSharedMemorySize, SMEM_BYTES);
    cudaFuncSetAttribute(gemm_hmma_kernel<1, I_DIM, H_DIM>,
                         cudaFuncAttributeMaxDynamicSharedMemorySize, SMEM_BYTES);

    // GEMM1 fused: inter = lut_silu(x@gw^T*sg) * (x@uw^T*su)  (4096x8192, K=2048)
    {
        dim3 grid(I_DIM / 64, T_DIM / 128);
        gemm_hmma_kernel<0, H_DIM, I_DIM><<<grid, 256, SMEM_BYTES>>>(
            xh, guwh, gus, interh);
    }
    // GEMM2: out = inter @ down_w^T * ds    (4096x2048, K=8192)
    {
        dim3 grid(H_DIM / 128, T_DIM / 128);
        gemm_hmma_kernel<1, I_DIM, H_DIM><<<grid, 256, SMEM_BYTES>>>(
            interh, dwh, ds, d_out);
    }
    (void)in_sizes; (void)n_in; (void)out_size;
}